// round 1
// baseline (speedup 1.0000x reference)
#include <cuda_runtime.h>
#include <cuda_bf16.h>
#include <cstddef>

// ---------------------------------------------------------------------------
// Problem: out = relu(x @ W + b1) @ W2 + b2
// where W[a,b] = sum_i sum_j (Z1^j g_i)[a] * (Zm1T^j h_i)[b]
//             = sum_i sum_j ge_i[a - j + 512] * hs_i[b + j]
//   ge_i[k] = g_i[k mod 512]                     (cyclic extension, k in [0,1024))
//   hs_i[k] = h_i[k]        for k < 512
//           = -h_i[k - 512] for k >= 512         (sign-folded negacyclic ext.)
//
// Shapes: x (65536,512) f32, G/H (512,4), b1 (512), W2 (512,512), b2 (512)
// ---------------------------------------------------------------------------

#define NDIM 512
#define RDIM 4
#define BATCH 65536

// Scratch (allocation-free rule: use __device__ globals)
__device__ float g_W[NDIM * NDIM];            // 1 MB
__device__ float g_h[(size_t)BATCH * NDIM];   // 128 MB

// ---------------------------------------------------------------------------
// Kernel 1: build W (512x512) from G,H.
// Grid (8,8), 256 threads. Each block computes a 64x64 tile of W; each thread
// a 4x4 register tile with sliding windows over the extended g/h arrays.
// ---------------------------------------------------------------------------
__global__ __launch_bounds__(256)
void krylov_w_kernel(const float* __restrict__ G, const float* __restrict__ H,
                     float* __restrict__ W) {
    __shared__ float ge[RDIM][1024];
    __shared__ float hs[RDIM][1024];

    const int tid = threadIdx.x;
    for (int idx = tid; idx < RDIM * 1024; idx += 256) {
        int i = idx >> 10;
        int k = idx & 1023;
        ge[i][k] = G[(k & (NDIM - 1)) * RDIM + i];
        hs[i][k] = (k < NDIM) ? H[k * RDIM + i] : -H[(k - NDIM) * RDIM + i];
    }
    __syncthreads();

    const int a0 = blockIdx.y * 64 + (tid >> 4) * 4;   // W row base for this thread
    const int b0 = blockIdx.x * 64 + (tid & 15) * 4;   // W col base for this thread

    float acc[4][4] = {};

    for (int i = 0; i < RDIM; ++i) {
        float ga[4], hb[4];
#pragma unroll
        for (int d = 0; d < 4; ++d) ga[d] = ge[i][512 + a0 + d];
#pragma unroll
        for (int e = 0; e < 4; ++e) hb[e] = hs[i][b0 + e];

#pragma unroll 4
        for (int j = 0; j < NDIM; ++j) {
#pragma unroll
            for (int d = 0; d < 4; ++d)
#pragma unroll
                for (int e = 0; e < 4; ++e)
                    acc[d][e] = fmaf(ga[d], hb[e], acc[d][e]);
            // slide windows for j+1 (loads stay in-bounds even at j=511)
            ga[3] = ga[2]; ga[2] = ga[1]; ga[1] = ga[0];
            ga[0] = ge[i][512 + a0 - (j + 1)];
            hb[0] = hb[1]; hb[1] = hb[2]; hb[2] = hb[3];
            hb[3] = hs[i][b0 + 3 + (j + 1)];
        }
    }

#pragma unroll
    for (int d = 0; d < 4; ++d)
#pragma unroll
        for (int e = 0; e < 4; ++e)
            W[(a0 + d) * NDIM + (b0 + e)] = acc[d][e];
}

// ---------------------------------------------------------------------------
// Kernel 2: C[M,512] = act(A[M,512] @ B[512,512] + bias)
// Block tile 128x128, K-chunk 32, 256 threads, 8x8 register tile per thread.
// relu flag selects activation.
// ---------------------------------------------------------------------------
__global__ __launch_bounds__(256)
void gemm_bias_act(const float* __restrict__ A, const float* __restrict__ B,
                   const float* __restrict__ bias, float* __restrict__ C,
                   int relu) {
    __shared__ float As[32][132];   // As[k][m] (transposed A chunk, padded)
    __shared__ float Bs[32][128];   // Bs[k][n]

    const int tid = threadIdx.x;
    const int m0 = blockIdx.y * 128;
    const int n0 = blockIdx.x * 128;
    const int tm = (tid >> 4) * 8;
    const int tn = (tid & 15) * 8;

    float acc[8][8] = {};

    for (int k0 = 0; k0 < NDIM; k0 += 32) {
        // Load A chunk (128 rows x 32 k) -> As[k][m]
#pragma unroll
        for (int q = 0; q < 4; ++q) {
            int f   = tid + q * 256;       // 0..1023 float4 slots
            int row = f >> 3;              // 8 float4 per row
            int c4  = (f & 7) << 2;
            float4 v = *(const float4*)&A[(size_t)(m0 + row) * NDIM + k0 + c4];
            As[c4 + 0][row] = v.x;
            As[c4 + 1][row] = v.y;
            As[c4 + 2][row] = v.z;
            As[c4 + 3][row] = v.w;
        }
        // Load B chunk (32 k x 128 n) -> Bs[k][n]
#pragma unroll
        for (int q = 0; q < 4; ++q) {
            int f   = tid + q * 256;
            int row = f >> 5;              // 32 float4 per row
            int c4  = (f & 31) << 2;
            *(float4*)&Bs[row][c4] =
                *(const float4*)&B[(size_t)(k0 + row) * NDIM + n0 + c4];
        }
        __syncthreads();

#pragma unroll 8
        for (int k = 0; k < 32; ++k) {
            float a[8], b[8];
            *(float4*)&a[0] = *(const float4*)&As[k][tm];
            *(float4*)&a[4] = *(const float4*)&As[k][tm + 4];
            *(float4*)&b[0] = *(const float4*)&Bs[k][tn];
            *(float4*)&b[4] = *(const float4*)&Bs[k][tn + 4];
#pragma unroll
            for (int d = 0; d < 8; ++d)
#pragma unroll
                for (int e = 0; e < 8; ++e)
                    acc[d][e] = fmaf(a[d], b[e], acc[d][e]);
        }
        __syncthreads();
    }

    // Epilogue: bias + optional relu, vectorized stores
    float bv[8];
#pragma unroll
    for (int e = 0; e < 8; ++e) bv[e] = __ldg(&bias[n0 + tn + e]);

#pragma unroll
    for (int d = 0; d < 8; ++d) {
#pragma unroll
        for (int e = 0; e < 8; e += 4) {
            float4 v;
            v.x = acc[d][e + 0] + bv[e + 0];
            v.y = acc[d][e + 1] + bv[e + 1];
            v.z = acc[d][e + 2] + bv[e + 2];
            v.w = acc[d][e + 3] + bv[e + 3];
            if (relu) {
                v.x = fmaxf(v.x, 0.f);
                v.y = fmaxf(v.y, 0.f);
                v.z = fmaxf(v.z, 0.f);
                v.w = fmaxf(v.w, 0.f);
            }
            *(float4*)&C[(size_t)(m0 + tm + d) * NDIM + n0 + tn + e] = v;
        }
    }
}

// ---------------------------------------------------------------------------
// Launch: W-builder, then stage-1 GEMM (relu) into scratch h, then stage-2.
// ---------------------------------------------------------------------------
extern "C" void kernel_launch(void* const* d_in, const int* in_sizes, int n_in,
                              void* d_out, int out_size) {
    const float* x  = (const float*)d_in[0];
    const float* G  = (const float*)d_in[1];
    const float* H  = (const float*)d_in[2];
    const float* b1 = (const float*)d_in[3];
    const float* W2 = (const float*)d_in[4];
    const float* b2 = (const float*)d_in[5];
    float* out = (float*)d_out;

    void *pW = nullptr, *ph = nullptr;
    cudaGetSymbolAddress(&pW, g_W);   // address query only; no alloc, capture-safe
    cudaGetSymbolAddress(&ph, g_h);
    float* Wbuf = (float*)pW;
    float* hbuf = (float*)ph;

    // 1) Build structured W (512x512)
    krylov_w_kernel<<<dim3(8, 8), 256>>>(G, H, Wbuf);

    // 2) h = relu(x @ W + b1)
    gemm_bias_act<<<dim3(NDIM / 128, BATCH / 128), 256>>>(x, Wbuf, b1, hbuf, 1);

    // 3) out = h @ W2 + b2
    gemm_bias_act<<<dim3(NDIM / 128, BATCH / 128), 256>>>(hbuf, W2, b2, out, 0);
}